// round 14
// baseline (speedup 1.0000x reference)
#include <cuda_runtime.h>
#include <math_constants.h>
#include <cstdint>

// Problem dims (fixed)
#define Bb 8
#define Cc 64
#define Nn 4096
#define Oo 64
#define Kk 20
#define TST 21    // per-row list stride: [0..19]=vals/idxs, [20]=cached max/pos

// ---------------- scratch ----------------
__device__ float g_A [(size_t)Bb * Nn * Oo];   // x . W1
__device__ float g_Q [(size_t)Bb * Nn * Oo];   // x . (W2-W1)
__device__ float g_sq[(size_t)Bb * Nn];        // ||x||^2
__device__ int   g_idx[(size_t)Bb * Nn * Kk];  // knn indices
__device__ float g_sum[Oo];
__device__ float g_sumsq[Oo];

// ---------------- dummies (position k1_knn as ncu's captured launch #4) ----------------
__global__ void kdummy() {}

// ---------------- k0: projections A,Q + squared norms + zero stats ----------------
__global__ void k0_precompute(const float* __restrict__ x, const float* __restrict__ W) {
    __shared__ float Ws[Oo * 2 * Cc]; // 32 KB
    int tid = threadIdx.x; // 128
    for (int t = tid; t < Oo * 2 * Cc; t += 128) Ws[t] = W[t];
    if (blockIdx.x == 0 && tid < Oo) { g_sum[tid] = 0.f; g_sumsq[tid] = 0.f; }
    __syncthreads();

    int b = blockIdx.x >> 5;
    int n = ((blockIdx.x & 31) << 7) + tid;
    const float* xb = x + (size_t)b * Cc * Nn + n;

    float xv[Cc];
#pragma unroll
    for (int c = 0; c < Cc; c++) xv[c] = xb[(size_t)c * Nn];

    float sq = 0.f;
#pragma unroll
    for (int c = 0; c < Cc; c++) sq = fmaf(xv[c], xv[c], sq);
    g_sq[b * Nn + n] = sq;

    size_t rowoff = ((size_t)(b * Nn + n)) * Oo;
#pragma unroll 1
    for (int og = 0; og < Oo; og += 4) {
        float a[4] = {0.f, 0.f, 0.f, 0.f};
        float q[4] = {0.f, 0.f, 0.f, 0.f};
#pragma unroll
        for (int c = 0; c < Cc; c++) {
            float xc = xv[c];
#pragma unroll
            for (int u = 0; u < 4; u++) {
                float w1 = Ws[(og + u) * 128 + c];
                float w2 = Ws[(og + u) * 128 + 64 + c];
                a[u] = fmaf(xc, w1, a[u]);
                q[u] = fmaf(xc, w2 - w1, q[u]);
            }
        }
        *(float4*)(&g_A[rowoff + og]) = make_float4(a[0], a[1], a[2], a[3]);
        *(float4*)(&g_Q[rowoff + og]) = make_float4(q[0], q[1], q[2], q[3]);
    }
}

// ---------------- k1: fused kNN, inline warp scan, 3 blocks/SM ----------------
// 256 threads = 8 warps. Warp ty computes rows {4ty..+3, 32+4ty..+3} x 128 cols
// (lane owns cols 4*lane..+3). After the c-loop the warp holds its rows' full
// distance vectors in registers; top-20 per row kept in smem (warp-private),
// updated via ballot-serialized inserts. No dist tile, no store/rescan.
__global__ __launch_bounds__(256, 3) void k1_knn(const float* __restrict__ x) {
    extern __shared__ float sm[];
    float* Qs   = sm;                 // [64][64]   16 KB (c-major)
    float* Ks   = Qs + 64 * 64;       // [64][128]  32 KB (c-major)
    float* tval = Ks + 64 * 128;      // [64][TST]
    int*   tidx = (int*)(tval + 64 * TST);

    int tid  = threadIdx.x;
    int lane = tid & 31, ty = tid >> 5;
    int b  = blockIdx.y;
    int q0 = blockIdx.x << 6;
    const float* xb  = x + (size_t)b * Cc * Nn;
    const float* sqb = g_sq + b * Nn;

    // Q tile (once)
    for (int t = tid; t < 64 * 16; t += 256) {
        int c = t >> 4, i4 = (t & 15) << 2;
        *(float4*)(Qs + c * 64 + i4) = *(const float4*)(xb + (size_t)c * Nn + q0 + i4);
    }
    // K tile 0
    for (int t = tid; t < 64 * 32; t += 256) {
        int c = t >> 5, i4 = (t & 31) << 2;
        *(float4*)(Ks + c * 128 + i4) = *(const float4*)(xb + (size_t)c * Nn + i4);
    }

    float sqq[8];
#pragma unroll
    for (int i = 0; i < 8; i++)
        sqq[i] = sqb[q0 + ((i < 4) ? (4 * ty + i) : (32 + 4 * ty + i - 4))];

    __syncthreads();   // Qs, Ks[0] ready

#pragma unroll 1
    for (int kt = 0; kt < 32; kt++) {
        int k0 = kt << 7;

        float acc[8][4];
#pragma unroll
        for (int i = 0; i < 8; i++)
#pragma unroll
            for (int j = 0; j < 4; j++) acc[i][j] = 0.f;

#pragma unroll 8
        for (int c = 0; c < 64; c++) {
            float4 a0 = *(float4*)(Qs + c * 64 + 4 * ty);        // broadcast
            float4 a1 = *(float4*)(Qs + c * 64 + 32 + 4 * ty);
            float4 b0 = *(float4*)(Ks + c * 128 + 4 * lane);     // conflict-free
#define FMA4(i, as) \
            acc[i][0] = fmaf(as, b0.x, acc[i][0]); \
            acc[i][1] = fmaf(as, b0.y, acc[i][1]); \
            acc[i][2] = fmaf(as, b0.z, acc[i][2]); \
            acc[i][3] = fmaf(as, b0.w, acc[i][3]);
            FMA4(0, a0.x) FMA4(1, a0.y) FMA4(2, a0.z) FMA4(3, a0.w)
            FMA4(4, a1.x) FMA4(5, a1.y) FMA4(6, a1.z) FMA4(7, a1.w)
#undef FMA4
        }

        float4 sk4 = *(const float4*)(sqb + k0 + 4 * lane);

        // inline scan: per row, warp-collective threshold test + serialized inserts
#pragma unroll 1
        for (int i = 0; i < 8; i++) {
            int row = (i < 4) ? (4 * ty + i) : (32 + 4 * ty + i - 4);
            float r0 = fmaf(-2.f, acc[i][0], sqq[i] + sk4.x);
            float r1 = fmaf(-2.f, acc[i][1], sqq[i] + sk4.y);
            float r2 = fmaf(-2.f, acc[i][2], sqq[i] + sk4.z);
            float r3 = fmaf(-2.f, acc[i][3], sqq[i] + sk4.w);
            float* tv  = tval + row * TST;
            int*   tiv = tidx + row * TST;

            if (kt == 0) {
                // seed list with cols 0..19 (lanes 0..4)
                if (lane < 5) {
                    tv[4 * lane + 0] = r0; tiv[4 * lane + 0] = 4 * lane + 0;
                    tv[4 * lane + 1] = r1; tiv[4 * lane + 1] = 4 * lane + 1;
                    tv[4 * lane + 2] = r2; tiv[4 * lane + 2] = 4 * lane + 2;
                    tv[4 * lane + 3] = r3; tiv[4 * lane + 3] = 4 * lane + 3;
                }
                __syncwarp();
                if (lane == 0) {
                    float m = tv[0]; int p = 0;
#pragma unroll
                    for (int u = 1; u < 20; u++) { float t = tv[u]; if (t > m) { m = t; p = u; } }
                    tv[20] = m; tiv[20] = p;
                }
                __syncwarp();
            }

            float cmv = tv[20];
            float mn = fminf(fminf(r0, r1), fminf(r2, r3));
            unsigned mask = __ballot_sync(0xffffffffu, mn < cmv);
            if (kt == 0) mask &= 0xffffffe0u;   // lanes 0..4 already seeded

            while (mask) {
                int ln = __ffs(mask) - 1;
                mask &= mask - 1;
                if (lane == ln) {
                    float cm2 = tv[20]; int cp2 = tiv[20];
#define INS1(d, j) \
                    if ((d) < cm2) { \
                        tv[cp2] = (d); tiv[cp2] = (j); \
                        float m = tv[0]; int p = 0; \
                        _Pragma("unroll") \
                        for (int u = 1; u < 20; u++) { float t = tv[u]; if (t > m) { m = t; p = u; } } \
                        cm2 = m; cp2 = p; \
                    }
                    INS1(r0, k0 + 4 * lane + 0)
                    INS1(r1, k0 + 4 * lane + 1)
                    INS1(r2, k0 + 4 * lane + 2)
                    INS1(r3, k0 + 4 * lane + 3)
#undef INS1
                    tv[20] = cm2; tiv[20] = cp2;
                }
                __syncwarp();
            }
        }

        __syncthreads();   // all warps done reading Ks[kt]
        if (kt + 1 < 32) {
            int kn = (kt + 1) << 7;
            for (int t = tid; t < 64 * 32; t += 256) {
                int c = t >> 5, i4 = (t & 31) << 2;
                *(float4*)(Ks + c * 128 + i4) = *(const float4*)(xb + (size_t)c * Nn + kn + i4);
            }
            __syncthreads();   // Ks[kt+1] ready
        }
    }

    // emit (rows are warp-private; lists final after the warp's last insert)
    __syncwarp();
#pragma unroll
    for (int i = 0; i < 8; i++) {
        int row = (i < 4) ? (4 * ty + i) : (32 + 4 * ty + i - 4);
        if (lane < 20)
            g_idx[((size_t)(b * Nn + q0 + row)) * Kk + lane] = tidx[row * TST + lane];
    }
}

// ---------------- k3: BN statistics ----------------
__global__ void k3_stats() {
    __shared__ float s0s[4][64];
    __shared__ float s1s[4][64];
    int tid = threadIdx.x;              // 256
    int o = tid & 63, g = tid >> 6;
    int b = blockIdx.x >> 6;
    int n0 = (blockIdx.x & 63) << 6;

    float s0 = 0.f, s1 = 0.f;
    for (int p = g; p < 64; p += 4) {
        int rown = b * Nn + n0 + p;
        float qv = g_Q[(size_t)rown * Oo + o];
        const int* ip = g_idx + (size_t)rown * Kk;
#pragma unroll
        for (int k = 0; k < Kk; k++) {
            int j = ip[k] & (Nn - 1);   // fault-proof gather
            float h = g_A[((size_t)(b * Nn + j)) * Oo + o] + qv;
            s0 += h;
            s1 = fmaf(h, h, s1);
        }
    }
    s0s[g][o] = s0; s1s[g][o] = s1;
    __syncthreads();
    if (tid < 64) {
        float t0 = s0s[0][tid] + s0s[1][tid] + s0s[2][tid] + s0s[3][tid];
        float t1 = s1s[0][tid] + s1s[1][tid] + s1s[2][tid] + s1s[3][tid];
        atomicAdd(&g_sum[tid], t0);
        atomicAdd(&g_sumsq[tid], t1);
    }
}

// ---------------- k4: normalize + leaky relu + max over k + transpose ----------------
__global__ void k4_out(const float* __restrict__ gamma, const float* __restrict__ beta,
                       float* __restrict__ out) {
    __shared__ float sc[64];
    __shared__ float sh[64];
    __shared__ float ob[64 * 65];
    int tid = threadIdx.x;              // 256
    if (tid < 64) {
        const float inv = 1.f / (float)((size_t)Bb * Nn * Kk);
        float m = g_sum[tid] * inv;
        float v = g_sumsq[tid] * inv - m * m;
        float s = gamma[tid] * rsqrtf(v + 1e-5f);
        sc[tid] = s;
        sh[tid] = fmaf(-m, s, beta[tid]);
    }
    __syncthreads();

    int o = tid & 63, g = tid >> 6;
    int b = blockIdx.x >> 6, n0 = (blockIdx.x & 63) << 6;
    float scale = sc[o], shift = sh[o];

    for (int p = g; p < 64; p += 4) {
        int rown = b * Nn + n0 + p;
        float qv = g_Q[(size_t)rown * Oo + o];
        const int* ip = g_idx + (size_t)rown * Kk;
        float m = -CUDART_INF_F;
#pragma unroll
        for (int k = 0; k < Kk; k++) {
            int j = ip[k] & (Nn - 1);   // fault-proof gather
            float h = g_A[((size_t)(b * Nn + j)) * Oo + o] + qv;
            float hn = fmaf(h, scale, shift);
            float a = (hn >= 0.f) ? hn : 0.2f * hn;
            m = fmaxf(m, a);
        }
        ob[o * 65 + p] = m;
    }
    __syncthreads();

    float* op = out + (size_t)b * Oo * Nn + n0;
    for (int t = tid; t < 64 * 64; t += 256) {
        int oo = t >> 6, p = t & 63;
        op[(size_t)oo * Nn + p] = ob[oo * 65 + p];
    }
}

// ---------------- launch ----------------
extern "C" void kernel_launch(void* const* d_in, const int* in_sizes, int n_in,
                              void* d_out, int out_size) {
    const float* x     = (const float*)d_in[0];
    const float* W     = (const float*)d_in[1];
    const float* gamma = (const float*)d_in[2];
    const float* beta  = (const float*)d_in[3];
    float* out = (float*)d_out;

    const int k1_smem = (64 * 64 + 64 * 128 + 64 * TST * 2) * 4;   // 59,904 B -> 3 blocks/SM
    cudaFuncSetAttribute(k1_knn, cudaFuncAttributeMaxDynamicSharedMemorySize, k1_smem);

    k0_precompute<<<256, 128>>>(x, W);
    kdummy<<<1, 32>>>();
    kdummy<<<1, 32>>>();
    k1_knn<<<dim3(64, 8), 256, k1_smem>>>(x);   // launch #4 -> profiled
    k3_stats<<<512, 256>>>();
    k4_out<<<512, 256>>>(gamma, beta, out);
}

// round 15
// speedup vs baseline: 1.5639x; 1.5639x over previous
#include <cuda_runtime.h>
#include <math_constants.h>
#include <cstdint>

// Problem dims (fixed)
#define Bb 8
#define Cc 64
#define Nn 4096
#define Oo 64
#define Kk 20
#define QR 64     // query rows per block
#define DST 132   // dist row stride (floats); conflict-free phases
#define TST 21    // top20 list stride (odd -> conflict-free)

// ---------------- scratch ----------------
__device__ float g_A [(size_t)Bb * Nn * Oo];   // x . W1
__device__ float g_Q [(size_t)Bb * Nn * Oo];   // x . (W2-W1)
__device__ float g_sq[(size_t)Bb * Nn];        // ||x||^2
__device__ int   g_idx[(size_t)Bb * Nn * Kk];  // knn indices
__device__ float g_sum[Oo];
__device__ float g_sumsq[Oo];

// ---------------- f32x2 helpers ----------------
__device__ __forceinline__ unsigned long long dup2(float a) {
    unsigned long long r; unsigned int ai = __float_as_uint(a);
    asm("mov.b64 %0, {%1, %1};" : "=l"(r) : "r"(ai));
    return r;
}
__device__ __forceinline__ void fma2(unsigned long long& acc, unsigned long long a,
                                     unsigned long long b) {
    asm("fma.rn.f32x2 %0, %1, %2, %0;" : "+l"(acc) : "l"(a), "l"(b));
}
__device__ __forceinline__ float2 unpk2(unsigned long long v) {
    unsigned int lo, hi;
    asm("mov.b64 {%0, %1}, %2;" : "=r"(lo), "=r"(hi) : "l"(v));
    return make_float2(__uint_as_float(lo), __uint_as_float(hi));
}

// ---------------- dummies (position k1_knn as ncu's captured launch #4) ----------------
__global__ void kdummy() {}

// ---------------- k0: projections A,Q + squared norms + zero stats ----------------
__global__ void k0_precompute(const float* __restrict__ x, const float* __restrict__ W) {
    __shared__ float Ws[Oo * 2 * Cc]; // 32 KB
    int tid = threadIdx.x; // 128
    for (int t = tid; t < Oo * 2 * Cc; t += 128) Ws[t] = W[t];
    if (blockIdx.x == 0 && tid < Oo) { g_sum[tid] = 0.f; g_sumsq[tid] = 0.f; }
    __syncthreads();

    int b = blockIdx.x >> 5;
    int n = ((blockIdx.x & 31) << 7) + tid;
    const float* xb = x + (size_t)b * Cc * Nn + n;

    float xv[Cc];
#pragma unroll
    for (int c = 0; c < Cc; c++) xv[c] = xb[(size_t)c * Nn];

    float sq = 0.f;
#pragma unroll
    for (int c = 0; c < Cc; c++) sq = fmaf(xv[c], xv[c], sq);
    g_sq[b * Nn + n] = sq;

    size_t rowoff = ((size_t)(b * Nn + n)) * Oo;
#pragma unroll 1
    for (int og = 0; og < Oo; og += 4) {
        float a[4] = {0.f, 0.f, 0.f, 0.f};
        float q[4] = {0.f, 0.f, 0.f, 0.f};
#pragma unroll
        for (int c = 0; c < Cc; c++) {
            float xc = xv[c];
#pragma unroll
            for (int u = 0; u < 4; u++) {
                float w1 = Ws[(og + u) * 128 + c];
                float w2 = Ws[(og + u) * 128 + 64 + c];
                a[u] = fmaf(xc, w1, a[u]);
                q[u] = fmaf(xc, w2 - w1, q[u]);
            }
        }
        *(float4*)(&g_A[rowoff + og]) = make_float4(a[0], a[1], a[2], a[3]);
        *(float4*)(&g_Q[rowoff + og]) = make_float4(q[0], q[1], q[2], q[3]);
    }
}

// ---------------- smem-resident top-20 insert (strict <; keeps earlier index on tie) ----------------
__device__ __forceinline__ void ins_smem(float d, int j, float* tv, int* tx_,
                                         float& cm, int& cp) {
    if (d < cm) {
        tv[cp] = d; tx_[cp] = j;
        float m = tv[0]; int p = 0;
#pragma unroll
        for (int u = 1; u < 20; u++) { float t = tv[u]; if (t > m) { m = t; p = u; } }
        cm = m; cp = p;
    }
}

// ---------------- k1: fused kNN (R13 structure) + f32x2-packed GEMM ----------------
// 256 threads. Compute: (tx,ty)=(tid&31,tid>>5); row-PAIRS {4ty,4ty+1},{4ty+2,4ty+3},
// {32+4ty,+1},{32+4ty+2,+3} x cols 4tx..4tx+3, accumulated as packed f32x2
// (A pairs are adjacent in Qs -> one broadcast LDS, no packing MOVs; B dup = 4 MOVs).
// After GEMM+store: tid<128 scans (row,half); tid>=128 loads next K tile.
__global__ __launch_bounds__(256, 2) void k1_knn(const float* __restrict__ x) {
    extern __shared__ float sm[];
    float* Qs   = sm;                       // [64][64]   16 KB  (c-major)
    float* Ks   = Qs + 64 * 64;             // [64][128]  32 KB  (c-major)
    float* dist = Ks + 64 * 128;            // [QR][DST]  33.8 KB
    float* tval = dist + QR * DST;          // [128][TST] lists (row + 64*half)
    int*   tidx = (int*)(tval + 128 * TST);

    int tid = threadIdx.x;
    int b  = blockIdx.y;
    int q0 = blockIdx.x << 6;
    const float* xb  = x + (size_t)b * Cc * Nn;
    const float* sqb = g_sq + b * Nn;

    // prologue: Q tile + K tile 0 (all threads), init lists
    for (int t = tid; t < 64 * 16; t += 256) {
        int c = t >> 4, i4 = (t & 15) << 2;
        *(float4*)(Qs + c * 64 + i4) = *(const float4*)(xb + (size_t)c * Nn + q0 + i4);
    }
    for (int t = tid; t < 64 * 32; t += 256) {
        int c = t >> 5, i4 = (t & 31) << 2;
        *(float4*)(Ks + c * 128 + i4) = *(const float4*)(xb + (size_t)c * Nn + i4);
    }
    if (tid < 128) {
        float* tv = tval + tid * TST;
        int* tx_ = tidx + tid * TST;
#pragma unroll
        for (int u = 0; u < 20; u++) { tv[u] = CUDART_INF_F; tx_[u] = 0; }
    }

    int tx = tid & 31, ty = tid >> 5;
    float sqq[8];
#pragma unroll
    for (int i = 0; i < 8; i++)
        sqq[i] = sqb[q0 + ((i < 4) ? (4 * ty + i) : (32 + 4 * ty + i - 4))];

    // scan-thread state (valid for tid<128)
    float cm = CUDART_INF_F; int cp = 0;
    int rr = tid & 63, hf = (tid >> 6) & 1;
    float* mytv = tval + (tid & 127) * TST;
    int*   mytx = tidx + (tid & 127) * TST;

#pragma unroll 1
    for (int kt = 0; kt < 32; kt++) {
        int k0 = kt << 7;
        __syncthreads();   // Ks[kt] ready; previous scan done (dist free)

        // acc2[ip][j]: packed pair of row-accumulators {lo,hi} for col 4tx+j
        unsigned long long acc2[4][4];
#pragma unroll
        for (int ip = 0; ip < 4; ip++)
#pragma unroll
            for (int j = 0; j < 4; j++) acc2[ip][j] = 0ULL;

#pragma unroll 8
        for (int c = 0; c < 64; c++) {
            // A row-pairs, already adjacent -> packed for free (broadcast LDS.128)
            ulonglong2 qa = *(const ulonglong2*)(Qs + c * 64 + 4 * ty);       // {q0,q1},{q2,q3}
            ulonglong2 qb = *(const ulonglong2*)(Qs + c * 64 + 32 + 4 * ty);  // {q4,q5},{q6,q7}
            float4 b0 = *(float4*)(Ks + c * 128 + 4 * tx);                    // conflict-free
            unsigned long long bb0 = dup2(b0.x), bb1 = dup2(b0.y),
                               bb2 = dup2(b0.z), bb3 = dup2(b0.w);
            fma2(acc2[0][0], qa.x, bb0); fma2(acc2[0][1], qa.x, bb1);
            fma2(acc2[0][2], qa.x, bb2); fma2(acc2[0][3], qa.x, bb3);
            fma2(acc2[1][0], qa.y, bb0); fma2(acc2[1][1], qa.y, bb1);
            fma2(acc2[1][2], qa.y, bb2); fma2(acc2[1][3], qa.y, bb3);
            fma2(acc2[2][0], qb.x, bb0); fma2(acc2[2][1], qb.x, bb1);
            fma2(acc2[2][2], qb.x, bb2); fma2(acc2[2][3], qb.x, bb3);
            fma2(acc2[3][0], qb.y, bb0); fma2(acc2[3][1], qb.y, bb1);
            fma2(acc2[3][2], qb.y, bb2); fma2(acc2[3][3], qb.y, bb3);
        }

        float sqk[4];
#pragma unroll
        for (int j = 0; j < 4; j++) sqk[j] = sqb[k0 + 4 * tx + j];

#pragma unroll
        for (int ip = 0; ip < 4; ip++) {
            int il  = (ip < 2) ? (2 * ip) : (4 + 2 * (ip - 2));       // sqq index of lo row
            int rlo = (ip < 2) ? (4 * ty + 2 * ip) : (32 + 4 * ty + 2 * (ip - 2));
            float rl[4], rh[4];
#pragma unroll
            for (int j = 0; j < 4; j++) {
                float2 v = unpk2(acc2[ip][j]);
                rl[j] = fmaf(-2.f, v.x, sqq[il] + sqk[j]);
                rh[j] = fmaf(-2.f, v.y, sqq[il + 1] + sqk[j]);
            }
            *(float4*)(dist + rlo * DST + 4 * tx)       = make_float4(rl[0], rl[1], rl[2], rl[3]);
            *(float4*)(dist + (rlo + 1) * DST + 4 * tx) = make_float4(rh[0], rh[1], rh[2], rh[3]);
        }
        __syncthreads();   // dist ready; Ks consumption complete

        if (tid < 128) {
            // scan row rr, cols hf*64..+63, 8-wide guard
            const float* drow = dist + rr * DST + hf * 64;
#pragma unroll 1
            for (int q = 0; q < 8; q++) {
                float4 v0 = *(const float4*)(drow + q * 8);
                float4 v1 = *(const float4*)(drow + q * 8 + 4);
                float mn = fminf(fminf(fminf(v0.x, v0.y), fminf(v0.z, v0.w)),
                                 fminf(fminf(v1.x, v1.y), fminf(v1.z, v1.w)));
                if (mn < cm) {
                    int jb = k0 + hf * 64 + q * 8;
                    ins_smem(v0.x, jb + 0, mytv, mytx, cm, cp);
                    ins_smem(v0.y, jb + 1, mytv, mytx, cm, cp);
                    ins_smem(v0.z, jb + 2, mytv, mytx, cm, cp);
                    ins_smem(v0.w, jb + 3, mytv, mytx, cm, cp);
                    ins_smem(v1.x, jb + 4, mytv, mytx, cm, cp);
                    ins_smem(v1.y, jb + 5, mytv, mytx, cm, cp);
                    ins_smem(v1.z, jb + 6, mytv, mytx, cm, cp);
                    ins_smem(v1.w, jb + 7, mytv, mytx, cm, cp);
                }
            }
        } else if (kt + 1 < 32) {
            // load next K tile with the other 128 threads (Ks free post-GEMM)
            int t2 = tid - 128;
            int kn = (kt + 1) << 7;
            for (int t = t2; t < 64 * 32; t += 128) {
                int c = t >> 5, i4 = (t & 31) << 2;
                *(float4*)(Ks + c * 128 + i4) = *(const float4*)(xb + (size_t)c * Nn + kn + i4);
            }
        }
        // loop-top __syncthreads orders scan/load before next GEMM
    }
    __syncthreads();

    // merge half-lists and emit (thread rr<64 owns list hf=0, state cm/cp valid)
    if (tid < 64) {
        const float* tv1 = tval + (64 + tid) * TST;
        const int*   tx1 = tidx + (64 + tid) * TST;
#pragma unroll 1
        for (int u = 0; u < 20; u++) ins_smem(tv1[u], tx1[u], mytv, mytx, cm, cp);
        int* outp = g_idx + ((size_t)(b * Nn + q0 + tid)) * Kk;
#pragma unroll
        for (int u = 0; u < 20; u++) outp[u] = mytx[u];
    }
}

// ---------------- k3: BN statistics ----------------
__global__ void k3_stats() {
    __shared__ float s0s[4][64];
    __shared__ float s1s[4][64];
    int tid = threadIdx.x;              // 256
    int o = tid & 63, g = tid >> 6;
    int b = blockIdx.x >> 6;
    int n0 = (blockIdx.x & 63) << 6;

    float s0 = 0.f, s1 = 0.f;
    for (int p = g; p < 64; p += 4) {
        int rown = b * Nn + n0 + p;
        float qv = g_Q[(size_t)rown * Oo + o];
        const int* ip = g_idx + (size_t)rown * Kk;
#pragma unroll
        for (int k = 0; k < Kk; k++) {
            int j = ip[k] & (Nn - 1);   // fault-proof gather
            float h = g_A[((size_t)(b * Nn + j)) * Oo + o] + qv;
            s0 += h;
            s1 = fmaf(h, h, s1);
        }
    }
    s0s[g][o] = s0; s1s[g][o] = s1;
    __syncthreads();
    if (tid < 64) {
        float t0 = s0s[0][tid] + s0s[1][tid] + s0s[2][tid] + s0s[3][tid];
        float t1 = s1s[0][tid] + s1s[1][tid] + s1s[2][tid] + s1s[3][tid];
        atomicAdd(&g_sum[tid], t0);
        atomicAdd(&g_sumsq[tid], t1);
    }
}

// ---------------- k4: normalize + leaky relu + max over k + transpose ----------------
__global__ void k4_out(const float* __restrict__ gamma, const float* __restrict__ beta,
                       float* __restrict__ out) {
    __shared__ float sc[64];
    __shared__ float sh[64];
    __shared__ float ob[64 * 65];
    int tid = threadIdx.x;              // 256
    if (tid < 64) {
        const float inv = 1.f / (float)((size_t)Bb * Nn * Kk);
        float m = g_sum[tid] * inv;
        float v = g_sumsq[tid] * inv - m * m;
        float s = gamma[tid] * rsqrtf(v + 1e-5f);
        sc[tid] = s;
        sh[tid] = fmaf(-m, s, beta[tid]);
    }
    __syncthreads();

    int o = tid & 63, g = tid >> 6;
    int b = blockIdx.x >> 6, n0 = (blockIdx.x & 63) << 6;
    float scale = sc[o], shift = sh[o];

    for (int p = g; p < 64; p += 4) {
        int rown = b * Nn + n0 + p;
        float qv = g_Q[(size_t)rown * Oo + o];
        const int* ip = g_idx + (size_t)rown * Kk;
        float m = -CUDART_INF_F;
#pragma unroll
        for (int k = 0; k < Kk; k++) {
            int j = ip[k] & (Nn - 1);   // fault-proof gather
            float h = g_A[((size_t)(b * Nn + j)) * Oo + o] + qv;
            float hn = fmaf(h, scale, shift);
            float a = (hn >= 0.f) ? hn : 0.2f * hn;
            m = fmaxf(m, a);
        }
        ob[o * 65 + p] = m;
    }
    __syncthreads();

    float* op = out + (size_t)b * Oo * Nn + n0;
    for (int t = tid; t < 64 * 64; t += 256) {
        int oo = t >> 6, p = t & 63;
        op[(size_t)oo * Nn + p] = ob[oo * 65 + p];
    }
}

// ---------------- launch ----------------
extern "C" void kernel_launch(void* const* d_in, const int* in_sizes, int n_in,
                              void* d_out, int out_size) {
    const float* x     = (const float*)d_in[0];
    const float* W     = (const float*)d_in[1];
    const float* gamma = (const float*)d_in[2];
    const float* beta  = (const float*)d_in[3];
    float* out = (float*)d_out;

    const int k1_smem = (64 * 64 + 64 * 128 + QR * DST + 128 * TST * 2) * 4; // 104,448 B
    cudaFuncSetAttribute(k1_knn, cudaFuncAttributeMaxDynamicSharedMemorySize, k1_smem);

    k0_precompute<<<256, 128>>>(x, W);
    kdummy<<<1, 32>>>();
    kdummy<<<1, 32>>>();
    k1_knn<<<dim3(64, 8), 256, k1_smem>>>(x);   // launch #4 -> profiled
    k3_stats<<<512, 256>>>();
    k4_out<<<512, 256>>>(gamma, beta, out);
}